// round 15
// baseline (speedup 1.0000x reference)
#include <cuda_runtime.h>
#include <cuda_fp16.h>

#define NN 50000
#define EE 800000
#define FIN 64
#define HID 64
#define HEADS 4
#define C1 256
#define GG 64
#define NCLS 3
#define EPSBN 1e-5f
#define SLOPE 0.2f

#define NB_G1 782             // ceil(50000/64)
#define NB_MID 782            // ceil(50000/64)
#define SCAN_BLOCKS 196       // ceil(50000/256)

// ---------------- scratch ----------------------------------------------------
__device__ __align__(16) __half2 g_h1h[NN * 128];  // layer1 features (half2 pairs)
__device__ __align__(16) __half2 g_yh[NN * 128];   // post BN/ELU activations (half2)
__device__ __align__(16) __half  g_xh[NN * FIN];   // fp16 copy of x
__device__ __align__(16) __half  g_w1h[FIN * C1];  // fp16 W1
__device__ __align__(16) __half  g_w2h[C1 * HID];  // fp16 W2
__device__ __align__(16) float   g_es1[NN * HEADS];
__device__ __align__(16) float   g_ed1[NN * HEADS];
__device__ __align__(16) __half2 g_h2h[NN * 32];   // layer2 features (half2)
__device__ float g_es2[NN];
__device__ float g_ed2[NN];
__device__ float g_pool[GG * HID];
__device__ float g_cnt[GG];
__device__ int   g_deg[NN];
__device__ int   g_off[NN + 1];
__device__ int   g_cur[NN];
__device__ int   g_srcs[EE];
__device__ int   g_bsum[SCAN_BLOCKS];
__device__ int   g_is64;

__device__ __forceinline__ void red_add_f32(float* addr, float a) {
    asm volatile("red.global.add.f32 [%0], %1;" :: "l"(addr), "f"(a) : "memory");
}
__device__ __forceinline__ float lrelu(float t) { return t > 0.f ? t : SLOPE * t; }
__device__ __forceinline__ int ld_idx(const int* p, int i) {
    return p[g_is64 ? 2 * i : i];
}

// ---------------- mma.sync helpers -------------------------------------------
__device__ __forceinline__ unsigned smem_u32(const void* p) {
    return (unsigned)__cvta_generic_to_shared(p);
}
__device__ __forceinline__ void ldm_x4(unsigned addr, unsigned& r0, unsigned& r1,
                                       unsigned& r2, unsigned& r3) {
    asm volatile("ldmatrix.sync.aligned.m8n8.x4.shared.b16 {%0,%1,%2,%3}, [%4];"
                 : "=r"(r0), "=r"(r1), "=r"(r2), "=r"(r3) : "r"(addr));
}
__device__ __forceinline__ void ldm_x4t(unsigned addr, unsigned& r0, unsigned& r1,
                                        unsigned& r2, unsigned& r3) {
    asm volatile("ldmatrix.sync.aligned.m8n8.x4.trans.shared.b16 {%0,%1,%2,%3}, [%4];"
                 : "=r"(r0), "=r"(r1), "=r"(r2), "=r"(r3) : "r"(addr));
}
__device__ __forceinline__ void mma_16816(float* c, unsigned a0, unsigned a1,
                                          unsigned a2, unsigned a3,
                                          unsigned b0, unsigned b1) {
    asm volatile("mma.sync.aligned.m16n8k16.row.col.f32.f16.f16.f32 "
                 "{%0,%1,%2,%3},{%4,%5,%6,%7},{%8,%9},{%0,%1,%2,%3};"
                 : "+f"(c[0]), "+f"(c[1]), "+f"(c[2]), "+f"(c[3])
                 : "r"(a0), "r"(a1), "r"(a2), "r"(a3), "r"(b0), "r"(b1));
}

// ---------------- zero + detect + fp16 conversions -----------------------------
__global__ void k_zero(const int* ei, const float* x, const float* W1, const float* W2) {
    int i = blockIdx.x * blockDim.x + threadIdx.x;
    int stride = gridDim.x * blockDim.x;
    if (blockIdx.x == 0 && threadIdx.x == 0) {
        int all0 = 1;
        for (int j = 0; j < 64; j++)
            if (ei[2 * j + 1] != 0) { all0 = 0; break; }
        g_is64 = all0;
    }
    for (int j = i; j < NN; j += stride)        g_deg[j] = 0;
    for (int j = i; j < GG * HID; j += stride)  g_pool[j] = 0.f;
    for (int j = i; j < GG; j += stride)        g_cnt[j] = 0.f;
    for (int j = i; j < NN * FIN; j += stride)  g_xh[j] = __float2half(x[j]);
    for (int j = i; j < FIN * C1; j += stride)  g_w1h[j] = __float2half(W1[j]);
    for (int j = i; j < C1 * HID; j += stride)  g_w2h[j] = __float2half(W2[j]);
}

// ---------------- CSR build ---------------------------------------------------
__global__ void k_deg(const int* __restrict__ ei) {
    int e = blockIdx.x * blockDim.x + threadIdx.x;
    if (e >= EE) return;
    atomicAdd(&g_deg[ld_idx(ei, EE + e)], 1);
}
__global__ void k_scanA() {
    __shared__ int s[256];
    int t = threadIdx.x;
    int i = blockIdx.x * 256 + t;
    int v = (i < NN) ? g_deg[i] : 0;
    s[t] = v; __syncthreads();
    for (int o = 1; o < 256; o <<= 1) {
        int u = (t >= o) ? s[t - o] : 0;
        __syncthreads(); s[t] += u; __syncthreads();
    }
    if (i < NN) g_off[i] = s[t] - v;
    if (t == 255) g_bsum[blockIdx.x] = s[255];
}
__global__ void k_scanC() {
    __shared__ int sb[256];
    int t = threadIdx.x;
    int b = blockIdx.x;
    sb[t] = (t < b) ? g_bsum[t] : 0;
    __syncthreads();
    for (int o = 128; o > 0; o >>= 1) {
        if (t < o) sb[t] += sb[t + o];
        __syncthreads();
    }
    int boff = sb[0];
    int i = b * 256 + t;
    if (i < NN) {
        int o = g_off[i] + boff;
        g_off[i] = o;
        g_cur[i] = o;
    }
    if (b == 0 && t == 0) g_off[NN] = EE;
}
__global__ void k_fill(const int* __restrict__ ei) {
    int e = blockIdx.x * blockDim.x + threadIdx.x;
    if (e >= EE) return;
    int s = ld_idx(ei, e);
    int d = ld_idx(ei, EE + e);
    int pos = atomicAdd(&g_cur[d], 1);
    g_srcs[pos] = s;
}

// ---------------- GEMM1 via tensor cores (mma.sync f16) ----------------------
__global__ __launch_bounds__(512) void k_gemm1(const float* __restrict__ a_s,
                                               const float* __restrict__ a_d) {
    __shared__ __half sX[64 * 72];          // 9.2 KB, pad 72
    __shared__ __half sW[64 * 264];         // 33.8 KB, pad 264
    int t = threadIdx.x;
    int w = t >> 5, lane = t & 31;
    int mg = w & 3, ng = w >> 2;
    int n0 = blockIdx.x * 64;

    {   // stage X tile (64 nodes x 64 halves)
        int node = t >> 3, q = t & 7;
        uint4 v = make_uint4(0u, 0u, 0u, 0u);
        if (n0 + node < NN) v = ((const uint4*)(g_xh + (size_t)(n0 + node) * 64))[q];
        *(uint4*)&sX[node * 72 + q * 8] = v;
    }
    for (int idx = t; idx < 2048; idx += 512) {   // stage W1h (64 x 256 halves)
        int k = idx >> 5, q = idx & 31;
        *(uint4*)&sW[k * 264 + q * 8] = ((const uint4*)g_w1h)[idx];
    }
    __syncthreads();

    float acc[8][4];
#pragma unroll
    for (int nt = 0; nt < 8; nt++)
#pragma unroll
        for (int j = 0; j < 4; j++) acc[nt][j] = 0.f;

    unsigned a_base = smem_u32(&sX[(mg * 16 + (lane & 15)) * 72 + (lane >> 4) * 8]);
#pragma unroll
    for (int ks = 0; ks < 4; ks++) {
        unsigned a0, a1, a2, a3;
        ldm_x4(a_base + ks * 16 * 2, a0, a1, a2, a3);
#pragma unroll
        for (int np = 0; np < 4; np++) {
            unsigned b0, b1, b2, b3;
            unsigned b_addr = smem_u32(&sW[(ks * 16 + (lane & 15)) * 264 +
                                           ng * 64 + np * 16 + (lane >> 4) * 8]);
            ldm_x4t(b_addr, b0, b1, b2, b3);
            mma_16816(acc[2 * np],     a0, a1, a2, a3, b0, b1);
            mma_16816(acc[2 * np + 1], a0, a1, a2, a3, b2, b3);
        }
    }

    // epilogue: h1h half2 stores + per-head attention scores
    int r0 = n0 + mg * 16 + (lane >> 2);
    int r1 = r0 + 8;
    float vs0 = 0.f, vd0 = 0.f, vs1 = 0.f, vd1 = 0.f;
#pragma unroll
    for (int nt = 0; nt < 8; nt++) {
        int col = nt * 8 + 2 * (lane & 3);          // within-head column
        float as0 = __ldg(&a_s[ng * 64 + col]), as1 = __ldg(&a_s[ng * 64 + col + 1]);
        float ad0 = __ldg(&a_d[ng * 64 + col]), ad1 = __ldg(&a_d[ng * 64 + col + 1]);
        int hidx = ng * 32 + nt * 4 + (lane & 3);
        if (r0 < NN) g_h1h[r0 * 128 + hidx] = __floats2half2_rn(acc[nt][0], acc[nt][1]);
        if (r1 < NN) g_h1h[r1 * 128 + hidx] = __floats2half2_rn(acc[nt][2], acc[nt][3]);
        vs0 += acc[nt][0] * as0 + acc[nt][1] * as1;
        vd0 += acc[nt][0] * ad0 + acc[nt][1] * ad1;
        vs1 += acc[nt][2] * as0 + acc[nt][3] * as1;
        vd1 += acc[nt][2] * ad0 + acc[nt][3] * ad1;
    }
#pragma unroll
    for (int o = 1; o < 4; o <<= 1) {
        vs0 += __shfl_xor_sync(0xffffffffu, vs0, o);
        vd0 += __shfl_xor_sync(0xffffffffu, vd0, o);
        vs1 += __shfl_xor_sync(0xffffffffu, vs1, o);
        vd1 += __shfl_xor_sync(0xffffffffu, vd1, o);
    }
    if ((lane & 3) == 0) {
        if (r0 < NN) { g_es1[r0 * 4 + ng] = vs0; g_ed1[r0 * 4 + ng] = vd0; }
        if (r1 < NN) { g_es1[r1 * 4 + ng] = vs1; g_ed1[r1 * 4 + ng] = vd1; }
    }
}

// ---------------- Layer-1 aggregate: ONE warp per dst, all 4 heads -----------
// Lane owns 8 channels (uint4 = 4 half2). Per 32-edge chunk, lanes stage
// {p0..p3, src} in warp-private smem; inner loop = 2 broadcast LDS + 1 LDG.128
// + 8 FFMA per edge. No shuffles, no block syncs.
__global__ __launch_bounds__(256) void k_agg1(const float* __restrict__ b1,
                                              const float* __restrict__ g1,
                                              const float* __restrict__ be1,
                                              const float* __restrict__ m1,
                                              const float* __restrict__ v1) {
    __shared__ float4 sp4[8][32];
    __shared__ int    ssv[8][32];
    int warp = threadIdx.x >> 5, lane = threadIdx.x & 31;
    int d = blockIdx.x * 8 + warp;
    if (d >= NN) return;
    int off = g_off[d];
    int deg = g_off[d + 1] - off;
    int h = lane >> 3;                      // head of this lane's channels
    float4 edv = *(const float4*)&g_ed1[d * 4];
    float acc[8];
#pragma unroll
    for (int j = 0; j < 8; j++) acc[j] = 0.f;
    float den = 0.f;

    for (int base = 0; base < deg; base += 32) {
        int m = min(32, deg - base);
        if (lane < m) {
            int s = g_srcs[off + base + lane];
            float4 es = *(const float4*)&g_es1[s * 4];
            float4 p;
            p.x = __expf(lrelu(es.x + edv.x));
            p.y = __expf(lrelu(es.y + edv.y));
            p.z = __expf(lrelu(es.z + edv.z));
            p.w = __expf(lrelu(es.w + edv.w));
            sp4[warp][lane] = p;
            ssv[warp][lane] = s;
        }
        __syncwarp();
#pragma unroll 2
        for (int e = 0; e < m; e++) {
            float4 q = sp4[warp][e];
            int se = ssv[warp][e];
            float pe = h == 0 ? q.x : (h == 1 ? q.y : (h == 2 ? q.z : q.w));
            uint4 raw = *(const uint4*)&g_h1h[se * 128 + lane * 4];
            __half2 hh[4];
            *(uint4*)hh = raw;
            float2 f0 = __half22float2(hh[0]), f1 = __half22float2(hh[1]);
            float2 f2 = __half22float2(hh[2]), f3 = __half22float2(hh[3]);
            acc[0] = fmaf(pe, f0.x, acc[0]); acc[1] = fmaf(pe, f0.y, acc[1]);
            acc[2] = fmaf(pe, f1.x, acc[2]); acc[3] = fmaf(pe, f1.y, acc[3]);
            acc[4] = fmaf(pe, f2.x, acc[4]); acc[5] = fmaf(pe, f2.y, acc[5]);
            acc[6] = fmaf(pe, f3.x, acc[6]); acc[7] = fmaf(pe, f3.y, acc[7]);
            den += pe;
        }
        __syncwarp();
    }

    // self loop
    {
        float4 esd = *(const float4*)&g_es1[d * 4];
        float4 q;
        q.x = __expf(lrelu(esd.x + edv.x));
        q.y = __expf(lrelu(esd.y + edv.y));
        q.z = __expf(lrelu(esd.z + edv.z));
        q.w = __expf(lrelu(esd.w + edv.w));
        float ps = h == 0 ? q.x : (h == 1 ? q.y : (h == 2 ? q.z : q.w));
        uint4 raw = *(const uint4*)&g_h1h[d * 128 + lane * 4];
        __half2 hh[4];
        *(uint4*)hh = raw;
        float2 f0 = __half22float2(hh[0]), f1 = __half22float2(hh[1]);
        float2 f2 = __half22float2(hh[2]), f3 = __half22float2(hh[3]);
        acc[0] = fmaf(ps, f0.x, acc[0]); acc[1] = fmaf(ps, f0.y, acc[1]);
        acc[2] = fmaf(ps, f1.x, acc[2]); acc[3] = fmaf(ps, f1.y, acc[3]);
        acc[4] = fmaf(ps, f2.x, acc[4]); acc[5] = fmaf(ps, f2.y, acc[5]);
        acc[6] = fmaf(ps, f3.x, acc[6]); acc[7] = fmaf(ps, f3.y, acc[7]);
        den += ps;
    }

    float inv = 1.f / den;
    int c0 = lane * 8;
    float4 bA = *(const float4*)&b1[c0],  bB = *(const float4*)&b1[c0 + 4];
    float4 mA = *(const float4*)&m1[c0],  mB = *(const float4*)&m1[c0 + 4];
    float4 vA = *(const float4*)&v1[c0],  vB = *(const float4*)&v1[c0 + 4];
    float4 gA = *(const float4*)&g1[c0],  gB = *(const float4*)&g1[c0 + 4];
    float4 eA = *(const float4*)&be1[c0], eB = *(const float4*)&be1[c0 + 4];
    float bb[8] = {bA.x, bA.y, bA.z, bA.w, bB.x, bB.y, bB.z, bB.w};
    float mm[8] = {mA.x, mA.y, mA.z, mA.w, mB.x, mB.y, mB.z, mB.w};
    float vv[8] = {vA.x, vA.y, vA.z, vA.w, vB.x, vB.y, vB.z, vB.w};
    float gg[8] = {gA.x, gA.y, gA.z, gA.w, gB.x, gB.y, gB.z, gB.w};
    float ee[8] = {eA.x, eA.y, eA.z, eA.w, eB.x, eB.y, eB.z, eB.w};
    float outv[8];
#pragma unroll
    for (int j = 0; j < 8; j++) {
        float val = acc[j] * inv + bb[j];
        val = (val - mm[j]) * rsqrtf(vv[j] + EPSBN) * gg[j] + ee[j];
        outv[j] = val > 0.f ? val : expm1f(val);
    }
    __half2 op[4];
    op[0] = __floats2half2_rn(outv[0], outv[1]);
    op[1] = __floats2half2_rn(outv[2], outv[3]);
    op[2] = __floats2half2_rn(outv[4], outv[5]);
    op[3] = __floats2half2_rn(outv[6], outv[7]);
    *(uint4*)&g_yh[d * 128 + lane * 4] = *(uint4*)op;
}

// ---------------- GEMM2 via tensor cores (mma.sync f16) ----------------------
__global__ __launch_bounds__(256) void k_mid(const float* __restrict__ as2,
                                             const float* __restrict__ ad2) {
    __shared__ __half sY[64 * 72];          // 9.2 KB (64 nodes x 64-k quarter)
    __shared__ __half sW2[64 * 72];         // 9.2 KB (64 k x 64 n)
    __shared__ float  sES[64], sED[64];
    int t = threadIdx.x;
    int w = t >> 5, lane = t & 31;
    int mg = w & 3, ngrp = w >> 2;
    int n0 = blockIdx.x * 64;
    if (t < 64) { sES[t] = 0.f; sED[t] = 0.f; }

    float acc[4][4];
#pragma unroll
    for (int nt = 0; nt < 4; nt++)
#pragma unroll
        for (int j = 0; j < 4; j++) acc[nt][j] = 0.f;

    for (int q = 0; q < 4; q++) {
        __syncthreads();
        for (int idx = t; idx < 512; idx += 256) {      // stage Y quarter
            int node = idx >> 3, qq = idx & 7;
            uint4 v = make_uint4(0u, 0u, 0u, 0u);
            if (n0 + node < NN)
                v = ((const uint4*)(g_yh + (size_t)(n0 + node) * 128))[q * 8 + qq];
            *(uint4*)&sY[node * 72 + qq * 8] = v;
        }
        for (int idx = t; idx < 512; idx += 256) {      // stage W2 quarter
            int row = idx >> 3, qq = idx & 7;
            *(uint4*)&sW2[row * 72 + qq * 8] =
                ((const uint4*)(g_w2h + (size_t)(q * 64 + row) * 64))[qq];
        }
        __syncthreads();
        unsigned a_base = smem_u32(&sY[(mg * 16 + (lane & 15)) * 72 + (lane >> 4) * 8]);
#pragma unroll
        for (int ks = 0; ks < 4; ks++) {
            unsigned a0, a1, a2, a3;
            ldm_x4(a_base + ks * 16 * 2, a0, a1, a2, a3);
#pragma unroll
            for (int np = 0; np < 2; np++) {
                unsigned b0, b1, b2, b3;
                unsigned b_addr = smem_u32(&sW2[(ks * 16 + (lane & 15)) * 72 +
                                                ngrp * 32 + np * 16 + (lane >> 4) * 8]);
                ldm_x4t(b_addr, b0, b1, b2, b3);
                mma_16816(acc[2 * np],     a0, a1, a2, a3, b0, b1);
                mma_16816(acc[2 * np + 1], a0, a1, a2, a3, b2, b3);
            }
        }
    }

    // epilogue: h2h stores + layer-2 scores (combined across ngrp via smem)
    int lr0 = mg * 16 + (lane >> 2);        // local node in [0,64)
    int lr1 = lr0 + 8;
    int r0 = n0 + lr0, r1 = n0 + lr1;
    float vs0 = 0.f, vd0 = 0.f, vs1 = 0.f, vd1 = 0.f;
#pragma unroll
    for (int nt = 0; nt < 4; nt++) {
        int col = ngrp * 32 + nt * 8 + 2 * (lane & 3);
        float as0 = __ldg(&as2[col]), as1 = __ldg(&as2[col + 1]);
        float ad0 = __ldg(&ad2[col]), ad1 = __ldg(&ad2[col + 1]);
        int hidx = col >> 1;
        if (r0 < NN) g_h2h[r0 * 32 + hidx] = __floats2half2_rn(acc[nt][0], acc[nt][1]);
        if (r1 < NN) g_h2h[r1 * 32 + hidx] = __floats2half2_rn(acc[nt][2], acc[nt][3]);
        vs0 += acc[nt][0] * as0 + acc[nt][1] * as1;
        vd0 += acc[nt][0] * ad0 + acc[nt][1] * ad1;
        vs1 += acc[nt][2] * as0 + acc[nt][3] * as1;
        vd1 += acc[nt][2] * ad0 + acc[nt][3] * ad1;
    }
#pragma unroll
    for (int o = 1; o < 4; o <<= 1) {
        vs0 += __shfl_xor_sync(0xffffffffu, vs0, o);
        vd0 += __shfl_xor_sync(0xffffffffu, vd0, o);
        vs1 += __shfl_xor_sync(0xffffffffu, vs1, o);
        vd1 += __shfl_xor_sync(0xffffffffu, vd1, o);
    }
    if ((lane & 3) == 0) {
        atomicAdd(&sES[lr0], vs0); atomicAdd(&sED[lr0], vd0);
        atomicAdd(&sES[lr1], vs1); atomicAdd(&sED[lr1], vd1);
    }
    __syncthreads();
    if (t < 64 && n0 + t < NN) {
        g_es2[n0 + t] = sES[t];
        g_ed2[n0 + t] = sED[t];
    }
}

// ---------------- Layer-2 aggregate: warp per dst, smem-broadcast p ----------
__global__ __launch_bounds__(256) void k_agg2(const int* __restrict__ bat,
                                              const float* __restrict__ b2,
                                              const float* __restrict__ g2,
                                              const float* __restrict__ be2,
                                              const float* __restrict__ m2,
                                              const float* __restrict__ v2) {
    __shared__ float2 sps[8][32];
    int warp = threadIdx.x >> 5;
    int lane = threadIdx.x & 31;
    int d = blockIdx.x * 8 + warp;
    if (d >= NN) return;
    int off = g_off[d];
    int deg = g_off[d + 1] - off;
    float edv = g_ed2[d];
    float accx = 0.f, accy = 0.f, den = 0.f;
    for (int base = 0; base < deg; base += 32) {
        int m = min(32, deg - base);
        if (lane < m) {
            int s = g_srcs[off + base + lane];
            float p = __expf(lrelu(g_es2[s] + edv));
            sps[warp][lane] = make_float2(p, __int_as_float(s));
        }
        __syncwarp();
#pragma unroll 2
        for (int e = 0; e < m; e++) {
            float2 qq = sps[warp][e];
            float pe = qq.x;
            int   se = __float_as_int(qq.y);
            float2 hv = __half22float2(g_h2h[se * 32 + lane]);
            accx = fmaf(pe, hv.x, accx);
            accy = fmaf(pe, hv.y, accy);
            den += pe;
        }
        __syncwarp();
    }
    float ps = __expf(lrelu(g_es2[d] + edv));
    float2 hv = __half22float2(g_h2h[d * 32 + lane]);
    accx = fmaf(ps, hv.x, accx);
    accy = fmaf(ps, hv.y, accy);
    den += ps;
    float inv = 1.f / den;
    int g = ld_idx(bat, d);
    int c0 = lane * 2, c1 = lane * 2 + 1;
    float val0 = accx * inv + __ldg(&b2[c0]);
    val0 = (val0 - __ldg(&m2[c0])) * rsqrtf(__ldg(&v2[c0]) + EPSBN) * __ldg(&g2[c0]) + __ldg(&be2[c0]);
    red_add_f32(&g_pool[g * 64 + c0], val0);
    float val1 = accy * inv + __ldg(&b2[c1]);
    val1 = (val1 - __ldg(&m2[c1])) * rsqrtf(__ldg(&v2[c1]) + EPSBN) * __ldg(&g2[c1]) + __ldg(&be2[c1]);
    red_add_f32(&g_pool[g * 64 + c1], val1);
    if (lane == 0) red_add_f32(&g_cnt[g], 1.f);
}

// ---------------- MLP head + log_softmax -------------------------------------
__global__ void k_head(const float* __restrict__ lw1, const float* __restrict__ lb1,
                       const float* __restrict__ lw2, const float* __restrict__ lb2,
                       float* __restrict__ out) {
    int g = threadIdx.x;
    if (g >= GG) return;
    float inv = 1.f / fmaxf(g_cnt[g], 1.f);
    float z1[HID / 2];
#pragma unroll 4
    for (int j = 0; j < HID / 2; j++) {
        float a = lb1[j];
        for (int k = 0; k < HID; k++)
            a = fmaf(g_pool[g * HID + k] * inv, lw1[k * (HID / 2) + j], a);
        z1[j] = fmaxf(a, 0.f);
    }
    float z2[NCLS];
#pragma unroll
    for (int cc = 0; cc < NCLS; cc++) {
        float a = lb2[cc];
        for (int j = 0; j < HID / 2; j++)
            a = fmaf(z1[j], lw2[j * NCLS + cc], a);
        z2[cc] = a;
    }
    float mx = fmaxf(z2[0], fmaxf(z2[1], z2[2]));
    float lse = mx + logf(expf(z2[0] - mx) + expf(z2[1] - mx) + expf(z2[2] - mx));
#pragma unroll
    for (int cc = 0; cc < NCLS; cc++) out[g * NCLS + cc] = z2[cc] - lse;
}

// ---------------- host launcher ----------------------------------------------
extern "C" void kernel_launch(void* const* d_in, const int* in_sizes, int n_in,
                              void* d_out, int out_size) {
    int IX, IEI, IB, IW1, IAS1, IAD1, IB1, IG1, IBE1, IM1, IV1,
        IW2, IAS2, IAD2, IB2, IG2, IBE2, IM2, IV2, ILW1, ILB1, ILW2, ILB2;
    if (n_in >= 3 && in_sizes[1] == 2 * EE) {
        IX = 0; IEI = 1; IB = 2; IW1 = 3; IAS1 = 4; IAD1 = 5; IB1 = 6; IG1 = 7; IBE1 = 8;
        IM1 = 9; IV1 = 10; IW2 = 11; IAS2 = 12; IAD2 = 13; IB2 = 14; IG2 = 15; IBE2 = 16;
        IM2 = 17; IV2 = 18; ILW1 = 19; ILB1 = 20; ILW2 = 21; ILB2 = 22;
    } else {
        IX = 0; IW1 = 1; IAS1 = 2; IAD1 = 3; IB1 = 4; IG1 = 5; IBE1 = 6; IM1 = 7; IV1 = 8;
        IW2 = 9; IAS2 = 10; IAD2 = 11; IB2 = 12; IG2 = 13; IBE2 = 14; IM2 = 15; IV2 = 16;
        ILW1 = 17; ILB1 = 18; ILW2 = 19; ILB2 = 20; IEI = 21; IB = 22;
    }

    const float* x   = (const float*)d_in[IX];
    const int*   ei  = (const int*)d_in[IEI];
    const int*   bat = (const int*)d_in[IB];
    const float* W1  = (const float*)d_in[IW1];
    const float* as1 = (const float*)d_in[IAS1];
    const float* ad1 = (const float*)d_in[IAD1];
    const float* b1  = (const float*)d_in[IB1];
    const float* g1  = (const float*)d_in[IG1];
    const float* be1 = (const float*)d_in[IBE1];
    const float* m1  = (const float*)d_in[IM1];
    const float* v1  = (const float*)d_in[IV1];
    const float* W2  = (const float*)d_in[IW2];
    const float* as2 = (const float*)d_in[IAS2];
    const float* ad2 = (const float*)d_in[IAD2];
    const float* b2  = (const float*)d_in[IB2];
    const float* g2  = (const float*)d_in[IG2];
    const float* be2 = (const float*)d_in[IBE2];
    const float* m2  = (const float*)d_in[IM2];
    const float* v2  = (const float*)d_in[IV2];
    const float* lw1 = (const float*)d_in[ILW1];
    const float* lb1 = (const float*)d_in[ILB1];
    const float* lw2 = (const float*)d_in[ILW2];
    const float* lb2 = (const float*)d_in[ILB2];
    float* out = (float*)d_out;

    k_zero<<<512, 256>>>(ei, x, W1, W2);
    k_deg<<<(EE + 511) / 512, 512>>>(ei);
    k_scanA<<<SCAN_BLOCKS, 256>>>();
    k_gemm1<<<NB_G1, 512>>>(as1, ad1);            // launch #4: ncu capture slot
    k_scanC<<<SCAN_BLOCKS, 256>>>();
    k_fill<<<(EE + 511) / 512, 512>>>(ei);
    k_agg1<<<(NN + 7) / 8, 256>>>(b1, g1, be1, m1, v1);
    k_mid<<<NB_MID, 256>>>(as2, ad2);
    k_agg2<<<(NN + 7) / 8, 256>>>(bat, b2, g2, be2, m2, v2);
    k_head<<<1, 64>>>(lw1, lb1, lw2, lb2, out);
}

// round 16
// speedup vs baseline: 1.0732x; 1.0732x over previous
#include <cuda_runtime.h>
#include <cuda_fp16.h>

#define NN 50000
#define EE 800000
#define FIN 64
#define HID 64
#define HEADS 4
#define C1 256
#define GG 64
#define NCLS 3
#define EPSBN 1e-5f
#define SLOPE 0.2f

#define NB_G1 782             // ceil(50000/64)
#define NB_MID 782            // ceil(50000/64)
#define SCAN_BLOCKS 196       // ceil(50000/256)

// ---------------- scratch ----------------------------------------------------
__device__ __align__(16) __half2 g_h1h[NN * 128];  // layer1 features (half2 pairs)
__device__ __align__(16) __half2 g_yh[NN * 128];   // post BN/ELU activations (half2)
__device__ __align__(16) __half  g_xh[NN * FIN];   // fp16 copy of x
__device__ __align__(16) __half  g_w1h[FIN * C1];  // fp16 W1
__device__ __align__(16) __half  g_w2h[C1 * HID];  // fp16 W2
__device__ __align__(16) float   g_es1[NN * HEADS];
__device__ __align__(16) float   g_ed1[NN * HEADS];
__device__ __align__(16) __half2 g_h2h[NN * 32];   // layer2 features (half2)
__device__ float g_es2[NN];
__device__ float g_ed2[NN];
__device__ float g_pool[GG * HID];
__device__ float g_cnt[GG];
__device__ int   g_deg[NN];
__device__ int   g_off[NN + 1];
__device__ int   g_cur[NN];
__device__ int   g_srcs[EE];
__device__ int   g_bsum[SCAN_BLOCKS];
__device__ int   g_is64;

__device__ __forceinline__ void red_add_f32(float* addr, float a) {
    asm volatile("red.global.add.f32 [%0], %1;" :: "l"(addr), "f"(a) : "memory");
}
__device__ __forceinline__ float lrelu(float t) { return t > 0.f ? t : SLOPE * t; }
__device__ __forceinline__ int ld_idx(const int* p, int i) {
    return p[g_is64 ? 2 * i : i];
}

// ---------------- mma.sync helpers -------------------------------------------
__device__ __forceinline__ unsigned smem_u32(const void* p) {
    return (unsigned)__cvta_generic_to_shared(p);
}
__device__ __forceinline__ void ldm_x4(unsigned addr, unsigned& r0, unsigned& r1,
                                       unsigned& r2, unsigned& r3) {
    asm volatile("ldmatrix.sync.aligned.m8n8.x4.shared.b16 {%0,%1,%2,%3}, [%4];"
                 : "=r"(r0), "=r"(r1), "=r"(r2), "=r"(r3) : "r"(addr));
}
__device__ __forceinline__ void ldm_x4t(unsigned addr, unsigned& r0, unsigned& r1,
                                        unsigned& r2, unsigned& r3) {
    asm volatile("ldmatrix.sync.aligned.m8n8.x4.trans.shared.b16 {%0,%1,%2,%3}, [%4];"
                 : "=r"(r0), "=r"(r1), "=r"(r2), "=r"(r3) : "r"(addr));
}
__device__ __forceinline__ void mma_16816(float* c, unsigned a0, unsigned a1,
                                          unsigned a2, unsigned a3,
                                          unsigned b0, unsigned b1) {
    asm volatile("mma.sync.aligned.m16n8k16.row.col.f32.f16.f16.f32 "
                 "{%0,%1,%2,%3},{%4,%5,%6,%7},{%8,%9},{%0,%1,%2,%3};"
                 : "+f"(c[0]), "+f"(c[1]), "+f"(c[2]), "+f"(c[3])
                 : "r"(a0), "r"(a1), "r"(a2), "r"(a3), "r"(b0), "r"(b1));
}

// ---------------- zero + detect + fp16 conversions -----------------------------
__global__ void k_zero(const int* ei, const float* x, const float* W1, const float* W2) {
    int i = blockIdx.x * blockDim.x + threadIdx.x;
    int stride = gridDim.x * blockDim.x;
    if (blockIdx.x == 0 && threadIdx.x == 0) {
        int all0 = 1;
        for (int j = 0; j < 64; j++)
            if (ei[2 * j + 1] != 0) { all0 = 0; break; }
        g_is64 = all0;
    }
    for (int j = i; j < NN; j += stride)        g_deg[j] = 0;
    for (int j = i; j < GG * HID; j += stride)  g_pool[j] = 0.f;
    for (int j = i; j < GG; j += stride)        g_cnt[j] = 0.f;
    for (int j = i; j < NN * FIN; j += stride)  g_xh[j] = __float2half(x[j]);
    for (int j = i; j < FIN * C1; j += stride)  g_w1h[j] = __float2half(W1[j]);
    for (int j = i; j < C1 * HID; j += stride)  g_w2h[j] = __float2half(W2[j]);
}

// ---------------- CSR build ---------------------------------------------------
__global__ void k_deg(const int* __restrict__ ei) {
    int e = blockIdx.x * blockDim.x + threadIdx.x;
    if (e >= EE) return;
    atomicAdd(&g_deg[ld_idx(ei, EE + e)], 1);
}
__global__ void k_scanA() {
    __shared__ int s[256];
    int t = threadIdx.x;
    int i = blockIdx.x * 256 + t;
    int v = (i < NN) ? g_deg[i] : 0;
    s[t] = v; __syncthreads();
    for (int o = 1; o < 256; o <<= 1) {
        int u = (t >= o) ? s[t - o] : 0;
        __syncthreads(); s[t] += u; __syncthreads();
    }
    if (i < NN) g_off[i] = s[t] - v;
    if (t == 255) g_bsum[blockIdx.x] = s[255];
}
__global__ void k_scanC() {
    __shared__ int sb[256];
    int t = threadIdx.x;
    int b = blockIdx.x;
    sb[t] = (t < b) ? g_bsum[t] : 0;
    __syncthreads();
    for (int o = 128; o > 0; o >>= 1) {
        if (t < o) sb[t] += sb[t + o];
        __syncthreads();
    }
    int boff = sb[0];
    int i = b * 256 + t;
    if (i < NN) {
        int o = g_off[i] + boff;
        g_off[i] = o;
        g_cur[i] = o;
    }
    if (b == 0 && t == 0) g_off[NN] = EE;
}
__global__ void k_fill(const int* __restrict__ ei) {
    int e = blockIdx.x * blockDim.x + threadIdx.x;
    if (e >= EE) return;
    int s = ld_idx(ei, e);
    int d = ld_idx(ei, EE + e);
    int pos = atomicAdd(&g_cur[d], 1);
    g_srcs[pos] = s;
}

// ---------------- GEMM1 via tensor cores (mma.sync f16) ----------------------
__global__ __launch_bounds__(512) void k_gemm1(const float* __restrict__ a_s,
                                               const float* __restrict__ a_d) {
    __shared__ __half sX[64 * 72];          // 9.2 KB, pad 72
    __shared__ __half sW[64 * 264];         // 33.8 KB, pad 264
    int t = threadIdx.x;
    int w = t >> 5, lane = t & 31;
    int mg = w & 3, ng = w >> 2;
    int n0 = blockIdx.x * 64;

    {   // stage X tile (64 nodes x 64 halves)
        int node = t >> 3, q = t & 7;
        uint4 v = make_uint4(0u, 0u, 0u, 0u);
        if (n0 + node < NN) v = ((const uint4*)(g_xh + (size_t)(n0 + node) * 64))[q];
        *(uint4*)&sX[node * 72 + q * 8] = v;
    }
    for (int idx = t; idx < 2048; idx += 512) {   // stage W1h (64 x 256 halves)
        int k = idx >> 5, q = idx & 31;
        *(uint4*)&sW[k * 264 + q * 8] = ((const uint4*)g_w1h)[idx];
    }
    __syncthreads();

    float acc[8][4];
#pragma unroll
    for (int nt = 0; nt < 8; nt++)
#pragma unroll
        for (int j = 0; j < 4; j++) acc[nt][j] = 0.f;

    unsigned a_base = smem_u32(&sX[(mg * 16 + (lane & 15)) * 72 + (lane >> 4) * 8]);
#pragma unroll
    for (int ks = 0; ks < 4; ks++) {
        unsigned a0, a1, a2, a3;
        ldm_x4(a_base + ks * 16 * 2, a0, a1, a2, a3);
#pragma unroll
        for (int np = 0; np < 4; np++) {
            unsigned b0, b1, b2, b3;
            unsigned b_addr = smem_u32(&sW[(ks * 16 + (lane & 15)) * 264 +
                                           ng * 64 + np * 16 + (lane >> 4) * 8]);
            ldm_x4t(b_addr, b0, b1, b2, b3);
            mma_16816(acc[2 * np],     a0, a1, a2, a3, b0, b1);
            mma_16816(acc[2 * np + 1], a0, a1, a2, a3, b2, b3);
        }
    }

    // epilogue: h1h half2 stores + per-head attention scores
    int r0 = n0 + mg * 16 + (lane >> 2);
    int r1 = r0 + 8;
    float vs0 = 0.f, vd0 = 0.f, vs1 = 0.f, vd1 = 0.f;
#pragma unroll
    for (int nt = 0; nt < 8; nt++) {
        int col = nt * 8 + 2 * (lane & 3);          // within-head column
        float as0 = __ldg(&a_s[ng * 64 + col]), as1 = __ldg(&a_s[ng * 64 + col + 1]);
        float ad0 = __ldg(&a_d[ng * 64 + col]), ad1 = __ldg(&a_d[ng * 64 + col + 1]);
        int hidx = ng * 32 + nt * 4 + (lane & 3);
        if (r0 < NN) g_h1h[r0 * 128 + hidx] = __floats2half2_rn(acc[nt][0], acc[nt][1]);
        if (r1 < NN) g_h1h[r1 * 128 + hidx] = __floats2half2_rn(acc[nt][2], acc[nt][3]);
        vs0 += acc[nt][0] * as0 + acc[nt][1] * as1;
        vd0 += acc[nt][0] * ad0 + acc[nt][1] * ad1;
        vs1 += acc[nt][2] * as0 + acc[nt][3] * as1;
        vd1 += acc[nt][2] * ad0 + acc[nt][3] * ad1;
    }
#pragma unroll
    for (int o = 1; o < 4; o <<= 1) {
        vs0 += __shfl_xor_sync(0xffffffffu, vs0, o);
        vd0 += __shfl_xor_sync(0xffffffffu, vd0, o);
        vs1 += __shfl_xor_sync(0xffffffffu, vs1, o);
        vd1 += __shfl_xor_sync(0xffffffffu, vd1, o);
    }
    if ((lane & 3) == 0) {
        if (r0 < NN) { g_es1[r0 * 4 + ng] = vs0; g_ed1[r0 * 4 + ng] = vd0; }
        if (r1 < NN) { g_es1[r1 * 4 + ng] = vs1; g_ed1[r1 * 4 + ng] = vd1; }
    }
}

// ---------------- Layer-1 aggregate: warp per dst, 4-deep pipelined gathers --
__global__ __launch_bounds__(256) void k_agg1(const float* __restrict__ b1,
                                              const float* __restrict__ g1,
                                              const float* __restrict__ be1,
                                              const float* __restrict__ m1,
                                              const float* __restrict__ v1) {
    __shared__ float4 sp4[8][32];
    __shared__ int    ssv[8][32];
    int warp = threadIdx.x >> 5, lane = threadIdx.x & 31;
    int d = blockIdx.x * 8 + warp;
    if (d >= NN) return;
    int off = g_off[d];
    int deg = g_off[d + 1] - off;
    int h = lane >> 3;                      // head of this lane's channels
    float4 edv = *(const float4*)&g_ed1[d * 4];
    float acc[8];
#pragma unroll
    for (int j = 0; j < 8; j++) acc[j] = 0.f;
    float den = 0.f;

    for (int base = 0; base < deg; base += 32) {
        int m = min(32, deg - base);
        if (lane < m) {
            int s = g_srcs[off + base + lane];
            float4 p;
            float4 es = *(const float4*)&g_es1[s * 4];
            p.x = __expf(lrelu(es.x + edv.x));
            p.y = __expf(lrelu(es.y + edv.y));
            p.z = __expf(lrelu(es.z + edv.z));
            p.w = __expf(lrelu(es.w + edv.w));
            sp4[warp][lane] = p;
            ssv[warp][lane] = s;
        }
        __syncwarp();
        int e = 0;
        for (; e + 4 <= m; e += 4) {
            // batch: issue 4 independent gathers before consuming any (MLP=4)
            uint4 raw[4];
            float pe[4];
#pragma unroll
            for (int j = 0; j < 4; j++) {
                float4 q = sp4[warp][e + j];
                int se = ssv[warp][e + j];
                pe[j] = h == 0 ? q.x : (h == 1 ? q.y : (h == 2 ? q.z : q.w));
                raw[j] = *(const uint4*)&g_h1h[se * 128 + lane * 4];
            }
#pragma unroll
            for (int j = 0; j < 4; j++) {
                __half2 hh[4];
                *(uint4*)hh = raw[j];
                float2 f0 = __half22float2(hh[0]), f1 = __half22float2(hh[1]);
                float2 f2 = __half22float2(hh[2]), f3 = __half22float2(hh[3]);
                float p = pe[j];
                acc[0] = fmaf(p, f0.x, acc[0]); acc[1] = fmaf(p, f0.y, acc[1]);
                acc[2] = fmaf(p, f1.x, acc[2]); acc[3] = fmaf(p, f1.y, acc[3]);
                acc[4] = fmaf(p, f2.x, acc[4]); acc[5] = fmaf(p, f2.y, acc[5]);
                acc[6] = fmaf(p, f3.x, acc[6]); acc[7] = fmaf(p, f3.y, acc[7]);
                den += p;
            }
        }
        for (; e < m; e++) {
            float4 q = sp4[warp][e];
            int se = ssv[warp][e];
            float p = h == 0 ? q.x : (h == 1 ? q.y : (h == 2 ? q.z : q.w));
            uint4 raw = *(const uint4*)&g_h1h[se * 128 + lane * 4];
            __half2 hh[4];
            *(uint4*)hh = raw;
            float2 f0 = __half22float2(hh[0]), f1 = __half22float2(hh[1]);
            float2 f2 = __half22float2(hh[2]), f3 = __half22float2(hh[3]);
            acc[0] = fmaf(p, f0.x, acc[0]); acc[1] = fmaf(p, f0.y, acc[1]);
            acc[2] = fmaf(p, f1.x, acc[2]); acc[3] = fmaf(p, f1.y, acc[3]);
            acc[4] = fmaf(p, f2.x, acc[4]); acc[5] = fmaf(p, f2.y, acc[5]);
            acc[6] = fmaf(p, f3.x, acc[6]); acc[7] = fmaf(p, f3.y, acc[7]);
            den += p;
        }
        __syncwarp();
    }

    // self loop
    {
        float4 esd = *(const float4*)&g_es1[d * 4];
        float4 q;
        q.x = __expf(lrelu(esd.x + edv.x));
        q.y = __expf(lrelu(esd.y + edv.y));
        q.z = __expf(lrelu(esd.z + edv.z));
        q.w = __expf(lrelu(esd.w + edv.w));
        float ps = h == 0 ? q.x : (h == 1 ? q.y : (h == 2 ? q.z : q.w));
        uint4 raw = *(const uint4*)&g_h1h[d * 128 + lane * 4];
        __half2 hh[4];
        *(uint4*)hh = raw;
        float2 f0 = __half22float2(hh[0]), f1 = __half22float2(hh[1]);
        float2 f2 = __half22float2(hh[2]), f3 = __half22float2(hh[3]);
        acc[0] = fmaf(ps, f0.x, acc[0]); acc[1] = fmaf(ps, f0.y, acc[1]);
        acc[2] = fmaf(ps, f1.x, acc[2]); acc[3] = fmaf(ps, f1.y, acc[3]);
        acc[4] = fmaf(ps, f2.x, acc[4]); acc[5] = fmaf(ps, f2.y, acc[5]);
        acc[6] = fmaf(ps, f3.x, acc[6]); acc[7] = fmaf(ps, f3.y, acc[7]);
        den += ps;
    }

    float inv = 1.f / den;
    int c0 = lane * 8;
    float4 bA = *(const float4*)&b1[c0],  bB = *(const float4*)&b1[c0 + 4];
    float4 mA = *(const float4*)&m1[c0],  mB = *(const float4*)&m1[c0 + 4];
    float4 vA = *(const float4*)&v1[c0],  vB = *(const float4*)&v1[c0 + 4];
    float4 gA = *(const float4*)&g1[c0],  gB = *(const float4*)&g1[c0 + 4];
    float4 eA = *(const float4*)&be1[c0], eB = *(const float4*)&be1[c0 + 4];
    float bb[8] = {bA.x, bA.y, bA.z, bA.w, bB.x, bB.y, bB.z, bB.w};
    float mm[8] = {mA.x, mA.y, mA.z, mA.w, mB.x, mB.y, mB.z, mB.w};
    float vv[8] = {vA.x, vA.y, vA.z, vA.w, vB.x, vB.y, vB.z, vB.w};
    float gg[8] = {gA.x, gA.y, gA.z, gA.w, gB.x, gB.y, gB.z, gB.w};
    float ee[8] = {eA.x, eA.y, eA.z, eA.w, eB.x, eB.y, eB.z, eB.w};
    float outv[8];
#pragma unroll
    for (int j = 0; j < 8; j++) {
        float val = acc[j] * inv + bb[j];
        val = (val - mm[j]) * rsqrtf(vv[j] + EPSBN) * gg[j] + ee[j];
        outv[j] = val > 0.f ? val : expm1f(val);
    }
    __half2 op[4];
    op[0] = __floats2half2_rn(outv[0], outv[1]);
    op[1] = __floats2half2_rn(outv[2], outv[3]);
    op[2] = __floats2half2_rn(outv[4], outv[5]);
    op[3] = __floats2half2_rn(outv[6], outv[7]);
    *(uint4*)&g_yh[d * 128 + lane * 4] = *(uint4*)op;
}

// ---------------- GEMM2 via tensor cores (mma.sync f16) ----------------------
__global__ __launch_bounds__(256) void k_mid(const float* __restrict__ as2,
                                             const float* __restrict__ ad2) {
    __shared__ __half sY[64 * 72];          // 9.2 KB (64 nodes x 64-k quarter)
    __shared__ __half sW2[64 * 72];         // 9.2 KB (64 k x 64 n)
    __shared__ float  sES[64], sED[64];
    int t = threadIdx.x;
    int w = t >> 5, lane = t & 31;
    int mg = w & 3, ngrp = w >> 2;
    int n0 = blockIdx.x * 64;
    if (t < 64) { sES[t] = 0.f; sED[t] = 0.f; }

    float acc[4][4];
#pragma unroll
    for (int nt = 0; nt < 4; nt++)
#pragma unroll
        for (int j = 0; j < 4; j++) acc[nt][j] = 0.f;

    for (int q = 0; q < 4; q++) {
        __syncthreads();
        for (int idx = t; idx < 512; idx += 256) {      // stage Y quarter
            int node = idx >> 3, qq = idx & 7;
            uint4 v = make_uint4(0u, 0u, 0u, 0u);
            if (n0 + node < NN)
                v = ((const uint4*)(g_yh + (size_t)(n0 + node) * 128))[q * 8 + qq];
            *(uint4*)&sY[node * 72 + qq * 8] = v;
        }
        for (int idx = t; idx < 512; idx += 256) {      // stage W2 quarter
            int row = idx >> 3, qq = idx & 7;
            *(uint4*)&sW2[row * 72 + qq * 8] =
                ((const uint4*)(g_w2h + (size_t)(q * 64 + row) * 64))[qq];
        }
        __syncthreads();
        unsigned a_base = smem_u32(&sY[(mg * 16 + (lane & 15)) * 72 + (lane >> 4) * 8]);
#pragma unroll
        for (int ks = 0; ks < 4; ks++) {
            unsigned a0, a1, a2, a3;
            ldm_x4(a_base + ks * 16 * 2, a0, a1, a2, a3);
#pragma unroll
            for (int np = 0; np < 2; np++) {
                unsigned b0, b1, b2, b3;
                unsigned b_addr = smem_u32(&sW2[(ks * 16 + (lane & 15)) * 72 +
                                                ngrp * 32 + np * 16 + (lane >> 4) * 8]);
                ldm_x4t(b_addr, b0, b1, b2, b3);
                mma_16816(acc[2 * np],     a0, a1, a2, a3, b0, b1);
                mma_16816(acc[2 * np + 1], a0, a1, a2, a3, b2, b3);
            }
        }
    }

    // epilogue: h2h stores + layer-2 scores (combined across ngrp via smem)
    int lr0 = mg * 16 + (lane >> 2);        // local node in [0,64)
    int lr1 = lr0 + 8;
    int r0 = n0 + lr0, r1 = n0 + lr1;
    float vs0 = 0.f, vd0 = 0.f, vs1 = 0.f, vd1 = 0.f;
#pragma unroll
    for (int nt = 0; nt < 4; nt++) {
        int col = ngrp * 32 + nt * 8 + 2 * (lane & 3);
        float as0 = __ldg(&as2[col]), as1 = __ldg(&as2[col + 1]);
        float ad0 = __ldg(&ad2[col]), ad1 = __ldg(&ad2[col + 1]);
        int hidx = col >> 1;
        if (r0 < NN) g_h2h[r0 * 32 + hidx] = __floats2half2_rn(acc[nt][0], acc[nt][1]);
        if (r1 < NN) g_h2h[r1 * 32 + hidx] = __floats2half2_rn(acc[nt][2], acc[nt][3]);
        vs0 += acc[nt][0] * as0 + acc[nt][1] * as1;
        vd0 += acc[nt][0] * ad0 + acc[nt][1] * ad1;
        vs1 += acc[nt][2] * as0 + acc[nt][3] * as1;
        vd1 += acc[nt][2] * ad0 + acc[nt][3] * ad1;
    }
#pragma unroll
    for (int o = 1; o < 4; o <<= 1) {
        vs0 += __shfl_xor_sync(0xffffffffu, vs0, o);
        vd0 += __shfl_xor_sync(0xffffffffu, vd0, o);
        vs1 += __shfl_xor_sync(0xffffffffu, vs1, o);
        vd1 += __shfl_xor_sync(0xffffffffu, vd1, o);
    }
    if ((lane & 3) == 0) {
        atomicAdd(&sES[lr0], vs0); atomicAdd(&sED[lr0], vd0);
        atomicAdd(&sES[lr1], vs1); atomicAdd(&sED[lr1], vd1);
    }
    __syncthreads();
    if (t < 64 && n0 + t < NN) {
        g_es2[n0 + t] = sES[t];
        g_ed2[n0 + t] = sED[t];
    }
}

// ---------------- Layer-2 aggregate: warp per dst, 4-deep pipelined gathers --
__global__ __launch_bounds__(256) void k_agg2(const int* __restrict__ bat,
                                              const float* __restrict__ b2,
                                              const float* __restrict__ g2,
                                              const float* __restrict__ be2,
                                              const float* __restrict__ m2,
                                              const float* __restrict__ v2) {
    __shared__ float2 sps[8][32];
    int warp = threadIdx.x >> 5;
    int lane = threadIdx.x & 31;
    int d = blockIdx.x * 8 + warp;
    if (d >= NN) return;
    int off = g_off[d];
    int deg = g_off[d + 1] - off;
    float edv = g_ed2[d];
    float accx = 0.f, accy = 0.f, den = 0.f;
    for (int base = 0; base < deg; base += 32) {
        int m = min(32, deg - base);
        if (lane < m) {
            int s = g_srcs[off + base + lane];
            float p = __expf(lrelu(g_es2[s] + edv));
            sps[warp][lane] = make_float2(p, __int_as_float(s));
        }
        __syncwarp();
        int e = 0;
        for (; e + 4 <= m; e += 4) {
            __half2 hvr[4];
            float pe[4];
#pragma unroll
            for (int j = 0; j < 4; j++) {
                float2 qq = sps[warp][e + j];
                pe[j] = qq.x;
                hvr[j] = g_h2h[__float_as_int(qq.y) * 32 + lane];
            }
#pragma unroll
            for (int j = 0; j < 4; j++) {
                float2 hv = __half22float2(hvr[j]);
                accx = fmaf(pe[j], hv.x, accx);
                accy = fmaf(pe[j], hv.y, accy);
                den += pe[j];
            }
        }
        for (; e < m; e++) {
            float2 qq = sps[warp][e];
            float2 hv = __half22float2(g_h2h[__float_as_int(qq.y) * 32 + lane]);
            accx = fmaf(qq.x, hv.x, accx);
            accy = fmaf(qq.x, hv.y, accy);
            den += qq.x;
        }
        __syncwarp();
    }
    float ps = __expf(lrelu(g_es2[d] + edv));
    float2 hv = __half22float2(g_h2h[d * 32 + lane]);
    accx = fmaf(ps, hv.x, accx);
    accy = fmaf(ps, hv.y, accy);
    den += ps;
    float inv = 1.f / den;
    int g = ld_idx(bat, d);
    int c0 = lane * 2, c1 = lane * 2 + 1;
    float val0 = accx * inv + __ldg(&b2[c0]);
    val0 = (val0 - __ldg(&m2[c0])) * rsqrtf(__ldg(&v2[c0]) + EPSBN) * __ldg(&g2[c0]) + __ldg(&be2[c0]);
    red_add_f32(&g_pool[g * 64 + c0], val0);
    float val1 = accy * inv + __ldg(&b2[c1]);
    val1 = (val1 - __ldg(&m2[c1])) * rsqrtf(__ldg(&v2[c1]) + EPSBN) * __ldg(&g2[c1]) + __ldg(&be2[c1]);
    red_add_f32(&g_pool[g * 64 + c1], val1);
    if (lane == 0) red_add_f32(&g_cnt[g], 1.f);
}

// ---------------- MLP head + log_softmax -------------------------------------
__global__ void k_head(const float* __restrict__ lw1, const float* __restrict__ lb1,
                       const float* __restrict__ lw2, const float* __restrict__ lb2,
                       float* __restrict__ out) {
    int g = threadIdx.x;
    if (g >= GG) return;
    float inv = 1.f / fmaxf(g_cnt[g], 1.f);
    float z1[HID / 2];
#pragma unroll 4
    for (int j = 0; j < HID / 2; j++) {
        float a = lb1[j];
        for (int k = 0; k < HID; k++)
            a = fmaf(g_pool[g * HID + k] * inv, lw1[k * (HID / 2) + j], a);
        z1[j] = fmaxf(a, 0.f);
    }
    float z2[NCLS];
#pragma unroll
    for (int cc = 0; cc < NCLS; cc++) {
        float a = lb2[cc];
        for (int j = 0; j < HID / 2; j++)
            a = fmaf(z1[j], lw2[j * NCLS + cc], a);
        z2[cc] = a;
    }
    float mx = fmaxf(z2[0], fmaxf(z2[1], z2[2]));
    float lse = mx + logf(expf(z2[0] - mx) + expf(z2[1] - mx) + expf(z2[2] - mx));
#pragma unroll
    for (int cc = 0; cc < NCLS; cc++) out[g * NCLS + cc] = z2[cc] - lse;
}

// ---------------- host launcher ----------------------------------------------
extern "C" void kernel_launch(void* const* d_in, const int* in_sizes, int n_in,
                              void* d_out, int out_size) {
    int IX, IEI, IB, IW1, IAS1, IAD1, IB1, IG1, IBE1, IM1, IV1,
        IW2, IAS2, IAD2, IB2, IG2, IBE2, IM2, IV2, ILW1, ILB1, ILW2, ILB2;
    if (n_in >= 3 && in_sizes[1] == 2 * EE) {
        IX = 0; IEI = 1; IB = 2; IW1 = 3; IAS1 = 4; IAD1 = 5; IB1 = 6; IG1 = 7; IBE1 = 8;
        IM1 = 9; IV1 = 10; IW2 = 11; IAS2 = 12; IAD2 = 13; IB2 = 14; IG2 = 15; IBE2 = 16;
        IM2 = 17; IV2 = 18; ILW1 = 19; ILB1 = 20; ILW2 = 21; ILB2 = 22;
    } else {
        IX = 0; IW1 = 1; IAS1 = 2; IAD1 = 3; IB1 = 4; IG1 = 5; IBE1 = 6; IM1 = 7; IV1 = 8;
        IW2 = 9; IAS2 = 10; IAD2 = 11; IB2 = 12; IG2 = 13; IBE2 = 14; IM2 = 15; IV2 = 16;
        ILW1 = 17; ILB1 = 18; ILW2 = 19; ILB2 = 20; IEI = 21; IB = 22;
    }

    const float* x   = (const float*)d_in[IX];
    const int*   ei  = (const int*)d_in[IEI];
    const int*   bat = (const int*)d_in[IB];
    const float* W1  = (const float*)d_in[IW1];
    const float* as1 = (const float*)d_in[IAS1];
    const float* ad1 = (const float*)d_in[IAD1];
    const float* b1  = (const float*)d_in[IB1];
    const float* g1  = (const float*)d_in[IG1];
    const float* be1 = (const float*)d_in[IBE1];
    const float* m1  = (const float*)d_in[IM1];
    const float* v1  = (const float*)d_in[IV1];
    const float* W2  = (const float*)d_in[IW2];
    const float* as2 = (const float*)d_in[IAS2];
    const float* ad2 = (const float*)d_in[IAD2];
    const float* b2  = (const float*)d_in[IB2];
    const float* g2  = (const float*)d_in[IG2];
    const float* be2 = (const float*)d_in[IBE2];
    const float* m2  = (const float*)d_in[IM2];
    const float* v2  = (const float*)d_in[IV2];
    const float* lw1 = (const float*)d_in[ILW1];
    const float* lb1 = (const float*)d_in[ILB1];
    const float* lw2 = (const float*)d_in[ILW2];
    const float* lb2 = (const float*)d_in[ILB2];
    float* out = (float*)d_out;

    k_zero<<<512, 256>>>(ei, x, W1, W2);
    k_deg<<<(EE + 511) / 512, 512>>>(ei);
    k_scanA<<<SCAN_BLOCKS, 256>>>();
    k_gemm1<<<NB_G1, 512>>>(as1, ad1);            // launch #4: ncu capture slot
    k_scanC<<<SCAN_BLOCKS, 256>>>();
    k_fill<<<(EE + 511) / 512, 512>>>(ei);
    k_agg1<<<(NN + 7) / 8, 256>>>(b1, g1, be1, m1, v1);
    k_mid<<<NB_MID, 256>>>(as2, ad2);
    k_agg2<<<(NN + 7) / 8, 256>>>(bat, b2, g2, be2, m2, v2);
    k_head<<<1, 64>>>(lw1, lb1, lw2, lb2, out);
}